// round 7
// baseline (speedup 1.0000x reference)
#include <cuda_runtime.h>

#define HID   64
#define BATCH 16
#define SEQ   512
#define VOCAB 32000
#define NTOK  (BATCH * SEQ * 2)     // 16384

// Scratch (no allocs allowed). All counters re-zeroed every launch by
// zero_kernel, so replays are self-consistent.
__device__ int   g_cnt_vb[VOCAB * BATCH];   // count[v][b], 2 MB
__device__ int   g_cnt_v[VOCAB];            // per-row total (dedup flag)
__device__ int   g_rowlist[NTOK];           // distinct rows (order varies; work identical)
__device__ int   g_nrows[1];
__device__ float g_acc[BATCH * HID];        // final per-batch hidden

// ---------------------------------------------------------------- zero
__global__ __launch_bounds__(256) void zero_kernel() {
    const int i = blockIdx.x * 256 + threadIdx.x;
    const int4 z = make_int4(0, 0, 0, 0);
    if (i < VOCAB * BATCH / 4) reinterpret_cast<int4*>(g_cnt_vb)[i] = z;
    if (i < VOCAB / 4)         reinterpret_cast<int4*>(g_cnt_v)[i]  = z;
    if (i < BATCH * HID / 4)   reinterpret_cast<float4*>(g_acc)[i] =
                                   make_float4(0.f, 0.f, 0.f, 0.f);
    if (i == 0) g_nrows[0] = 0;
}

// ---------------------------------------------------------------- histogram
// Build count[v][b] and the distinct-row worklist. Int atomics only.
__global__ __launch_bounds__(256) void hist_kernel(
    const int* __restrict__ s1, const int* __restrict__ s2)
{
    const int t = blockIdx.x * 256 + threadIdx.x;    // 0..16383
    const int b = t >> 10;
    const int l = t & 1023;
    const int v = (l < SEQ) ? s1[b * SEQ + l] : s2[b * SEQ + (l - SEQ)];
    atomicAdd(&g_cnt_vb[v * BATCH + b], 1);
    if (atomicAdd(&g_cnt_v[v], 1) == 0) {
        const int pos = atomicAdd(&g_nrows[0], 1);
        g_rowlist[pos] = v;
    }
}

// ---------------------------------------------------------------- gather
// One 256-thread block per DISTINCT vocab row: read 16 KB once, contract sos
// over w, then accumulate (count * vec) into each using batch via atomics.
// Thread tid loads float4 f = tid+256j: h-group = tid&15 (4 h values),
// w = (tid>>4)+16j -> one float4 accumulator per thread.
__global__ __launch_bounds__(256) void gather_kernel(
    const float* __restrict__ embed,
    const float* __restrict__ sos)
{
    __shared__ float  s_sos[HID];
    __shared__ int    s_cnt[BATCH];
    __shared__ int    s_v;
    __shared__ float4 red[256];

    const int tid = threadIdx.x;

    if (tid == 0) {
        const int n = g_nrows[0];
        s_v = (blockIdx.x < n) ? g_rowlist[blockIdx.x] : -1;
    }
    if (tid < HID) s_sos[tid] = sos[tid];
    __syncthreads();

    const int v = s_v;
    if (v < 0) return;

    if (tid < BATCH) s_cnt[tid] = g_cnt_vb[v * BATCH + tid];

    const float s0 = s_sos[tid >> 4];
    const float sA = s_sos[(tid >> 4) + 16];
    const float sB = s_sos[(tid >> 4) + 32];
    const float sC = s_sos[(tid >> 4) + 48];

    const float4* row = reinterpret_cast<const float4*>(embed)
                        + ((long long)v << 10);
    const float4 v0 = __ldg(&row[tid      ]);
    const float4 v1 = __ldg(&row[tid + 256]);
    const float4 v2 = __ldg(&row[tid + 512]);
    const float4 v3 = __ldg(&row[tid + 768]);

    float4 acc;
    acc.x = s0 * v0.x; acc.y = s0 * v0.y; acc.z = s0 * v0.z; acc.w = s0 * v0.w;
    acc.x = fmaf(sA, v1.x, acc.x); acc.y = fmaf(sA, v1.y, acc.y);
    acc.z = fmaf(sA, v1.z, acc.z); acc.w = fmaf(sA, v1.w, acc.w);
    acc.x = fmaf(sB, v2.x, acc.x); acc.y = fmaf(sB, v2.y, acc.y);
    acc.z = fmaf(sB, v2.z, acc.z); acc.w = fmaf(sB, v2.w, acc.w);
    acc.x = fmaf(sC, v3.x, acc.x); acc.y = fmaf(sC, v3.y, acc.y);
    acc.z = fmaf(sC, v3.z, acc.z); acc.w = fmaf(sC, v3.w, acc.w);

    red[tid] = acc;
    __syncthreads();

    // Threads 0..15: final float4 for h-group tid (sum 16 w-partials), then
    // scatter count-weighted contributions into each using batch.
    if (tid < 16) {
        float4 sum = make_float4(0.f, 0.f, 0.f, 0.f);
        #pragma unroll
        for (int j = 0; j < 16; j++) {
            const float4 p = red[tid + (j << 4)];
            sum.x += p.x; sum.y += p.y; sum.z += p.z; sum.w += p.w;
        }
        #pragma unroll
        for (int b = 0; b < BATCH; b++) {
            const int c = s_cnt[b];
            if (c) {
                const float f = (float)c;
                float* dst = &g_acc[b * HID + (tid << 2)];
                atomicAdd(dst + 0, f * sum.x);
                atomicAdd(dst + 1, f * sum.y);
                atomicAdd(dst + 2, f * sum.z);
                atomicAdd(dst + 3, f * sum.w);
            }
        }
    }
}

// ---------------------------------------------------------------- MLP
// One block per batch. w1 staged transposed (pad-65, conflict-free).
#define W1T_STRIDE 65
__global__ __launch_bounds__(256) void mlp_kernel(
    const float* __restrict__ w1,
    const float* __restrict__ b1,
    const float* __restrict__ w2,
    const float* __restrict__ b2,
    float*       __restrict__ out)
{
    __shared__ float w1t[HID * W1T_STRIDE];
    __shared__ float sh[HID];
    __shared__ float sx[HID];

    const int b   = blockIdx.x;
    const int tid = threadIdx.x;

    #pragma unroll
    for (int j = 0; j < 16; j++) {
        const int idx = tid + 256 * j;            // 0..4095
        w1t[(idx & 63) * W1T_STRIDE + (idx >> 6)] = w1[idx];
    }
    if (tid < HID) sh[tid] = g_acc[b * HID + tid];
    __syncthreads();

    if (tid < HID) {
        float sum = b1[tid];
        #pragma unroll
        for (int k = 0; k < HID; k++)
            sum = fmaf(sh[k], w1t[k * W1T_STRIDE + tid], sum);
        sx[tid] = fmaxf(sum, 0.0f);
    }
    __syncthreads();

    if (tid < 2) {
        float s2 = b2[tid];
        #pragma unroll
        for (int k = 0; k < HID; k++)
            s2 = fmaf(sx[k], w2[tid * HID + k], s2);
        out[b * 2 + tid] = s2;
    }
}

extern "C" void kernel_launch(void* const* d_in, const int* in_sizes, int n_in,
                              void* d_out, int out_size)
{
    const int*   s1    = (const int*)  d_in[0];
    const int*   s2    = (const int*)  d_in[1];
    const float* embed = (const float*)d_in[2];
    const float* sos   = (const float*)d_in[3];
    const float* w1    = (const float*)d_in[4];
    const float* b1    = (const float*)d_in[5];
    const float* w2    = (const float*)d_in[6];
    const float* b2    = (const float*)d_in[7];
    float* out = (float*)d_out;

    zero_kernel<<<VOCAB * BATCH / 4 / 256 + 1, 256>>>();
    hist_kernel<<<NTOK / 256, 256>>>(s1, s2);
    gather_kernel<<<NTOK, 256>>>(embed, sos);
    mlp_kernel<<<BATCH, 256>>>(w1, b1, w2, b2, out);
}